// round 15
// baseline (speedup 1.0000x reference)
#include <cuda_runtime.h>

#define NE      262144      // edges
#define NMAT_SH 13          // log2(8192)
#define EPSV    1e-8f

#define NBLOCKS  256
#define NTHREADS 128
#define EPT      8                       // edges per thread: 8 pos + 8 neg gathers
#define EPB      (NTHREADS * EPT)        // 1024 edges per block; NBLOCKS*EPB == NE

#define FXSCALE 16777216.0               // 2^24 fixed-point scale

// Deterministic integer accumulator + completion ticket (device globals).
__device__ unsigned long long g_acc;     // zero-init; reset by last block
__device__ unsigned int       g_count;

// Random gather, non-coherent, with an L2 evict-last cache policy.
__device__ __forceinline__ float ldg_evict_last(const float* p, unsigned long long pol) {
    float v;
    asm volatile("ld.global.nc.L2::cache_hint.f32 %0, [%1], %2;"
                 : "=f"(v) : "l"(p), "l"(pol));
    return v;
}

__global__ void __launch_bounds__(NTHREADS, 1)
fused_loss_kernel(const float* __restrict__ adj,
                  const int*   __restrict__ edge_index,   // [2, E]
                  const int*   __restrict__ neg_edges,    // [E, 2]
                  const float* __restrict__ codebook,
                  float*       __restrict__ out)
{
    const int tid = threadIdx.x;
    const int bid = blockIdx.x;
    const int e0  = bid * EPB + EPT * tid;   // this thread: edges e0..e0+7

    unsigned long long pol;
    asm volatile("createpolicy.fractional.L2::evict_last.b64 %0, 1.0;" : "=l"(pol));

    // ---- Phase 1: coalesced vector index loads (int4), then 16 gathers back-to-back ----
    const int4 sA = __ldg((const int4*)&edge_index[e0]);
    const int4 sB = __ldg((const int4*)&edge_index[e0 + 4]);
    const int4 dA = __ldg((const int4*)&edge_index[NE + e0]);
    const int4 dB = __ldg((const int4*)&edge_index[NE + e0 + 4]);
    const int4 n0 = __ldg((const int4*)&neg_edges[2 * e0]);       // (r,c) pairs 0,1
    const int4 n1 = __ldg((const int4*)&neg_edges[2 * e0 + 4]);   // pairs 2,3
    const int4 n2 = __ldg((const int4*)&neg_edges[2 * e0 + 8]);   // pairs 4,5
    const int4 n3 = __ldg((const int4*)&neg_edges[2 * e0 + 12]);  // pairs 6,7

    // 32-bit flat indices (N*N = 2^26). All 16 gathers issued before any use,
    // every index and result a named scalar (no local-memory demotion).
    const float p0 = ldg_evict_last(&adj[(sA.x << NMAT_SH) + dA.x], pol);
    const float p1 = ldg_evict_last(&adj[(sA.y << NMAT_SH) + dA.y], pol);
    const float p2 = ldg_evict_last(&adj[(sA.z << NMAT_SH) + dA.z], pol);
    const float p3 = ldg_evict_last(&adj[(sA.w << NMAT_SH) + dA.w], pol);
    const float p4 = ldg_evict_last(&adj[(sB.x << NMAT_SH) + dB.x], pol);
    const float p5 = ldg_evict_last(&adj[(sB.y << NMAT_SH) + dB.y], pol);
    const float p6 = ldg_evict_last(&adj[(sB.z << NMAT_SH) + dB.z], pol);
    const float p7 = ldg_evict_last(&adj[(sB.w << NMAT_SH) + dB.w], pol);
    const float q0 = ldg_evict_last(&adj[(n0.x << NMAT_SH) + n0.y], pol);
    const float q1 = ldg_evict_last(&adj[(n0.z << NMAT_SH) + n0.w], pol);
    const float q2 = ldg_evict_last(&adj[(n1.x << NMAT_SH) + n1.y], pol);
    const float q3 = ldg_evict_last(&adj[(n1.z << NMAT_SH) + n1.w], pol);
    const float q4 = ldg_evict_last(&adj[(n2.x << NMAT_SH) + n2.y], pol);
    const float q5 = ldg_evict_last(&adj[(n2.z << NMAT_SH) + n2.w], pol);
    const float q6 = ldg_evict_last(&adj[(n3.x << NMAT_SH) + n3.y], pol);
    const float q7 = ldg_evict_last(&adj[(n3.z << NMAT_SH) + n3.w], pol);

    // ---- Phase 2: fold 16 terms into FOUR logs (each 4-term product in [1e-32,1]) ----
    float pr0 = ((p0 + EPSV) * (p1 + EPSV)) * ((p2 + EPSV) * (p3 + EPSV));
    float pr1 = ((p4 + EPSV) * (p5 + EPSV)) * ((p6 + EPSV) * (p7 + EPSV));
    float qr0 = ((1.0f - q0 + EPSV) * (1.0f - q1 + EPSV))
              * ((1.0f - q2 + EPSV) * (1.0f - q3 + EPSV));
    float qr1 = ((1.0f - q4 + EPSV) * (1.0f - q5 + EPSV))
              * ((1.0f - q6 + EPSV) * (1.0f - q7 + EPSV));
    float acc = (__logf(pr0) + __logf(pr1)) + (__logf(qr0) + __logf(qr1));

    // ---- Phase 3: warp + block reduction ----
#pragma unroll
    for (int off = 16; off > 0; off >>= 1)
        acc += __shfl_down_sync(0xFFFFFFFFu, acc, off);

    __shared__ float s_acc[NTHREADS / 32];
    const int lane = tid & 31;
    const int wid  = tid >> 5;
    if (lane == 0) s_acc[wid] = acc;
    __syncthreads();

    if (tid == 0) {
        double dsum = 0.0;
#pragma unroll
        for (int w = 0; w < NTHREADS / 32; w++) dsum += (double)s_acc[w];

        // Exact, order-independent integer accumulation (deterministic).
        atomicAdd(&g_acc, (unsigned long long)llrint(dsum * FXSCALE));
        __threadfence();
        unsigned int ticket = atomicAdd(&g_count, 1u);

        // ---- Phase 4: last block finalizes (tiny tail) ----
        if (ticket == NBLOCKS - 1) {
            unsigned long long u = atomicAdd(&g_acc, 0ULL);   // strong read
            double total = (double)(long long)u / FXSCALE;
            double loss  = -total / (double)NE
                         + (double)codebook[0] + (double)codebook[1]
                         + (double)codebook[2] + (double)codebook[3];
            out[0] = (float)loss;
            // Reset scratch for next graph replay (stream-ordered).
            g_acc = 0ULL;
            __threadfence();
            g_count = 0;
        }
    }
}

extern "C" void kernel_launch(void* const* d_in, const int* in_sizes, int n_in,
                              void* d_out, int out_size)
{
    const float* adj        = (const float*)d_in[0];   // [N*N] fp32
    const float* codebook   = (const float*)d_in[1];   // [6] fp32
    const int*   edge_index = (const int*)d_in[2];     // [2*E] int32
    const int*   neg_edges  = (const int*)d_in[3];     // [E*2] int32
    float* out = (float*)d_out;

    fused_loss_kernel<<<NBLOCKS, NTHREADS>>>(adj, edge_index, neg_edges, codebook, out);
}

// round 16
// speedup vs baseline: 1.0226x; 1.0226x over previous
#include <cuda_runtime.h>

#define NE      262144      // edges
#define NMAT_SH 13          // log2(8192)
#define EPSV    1e-8f

#define NBLOCKS  256
#define NTHREADS 128
#define EPT      8                       // edges per thread: 8 pos + 8 neg gathers
#define EPB      (NTHREADS * EPT)        // 1024 edges per block; NBLOCKS*EPB == NE

#define FXSCALE 16777216.0               // 2^24 fixed-point scale

// Deterministic integer accumulator + completion ticket (device globals).
__device__ unsigned long long g_acc;     // zero-init; reset by last block
__device__ unsigned int       g_count;

// Random gather, non-coherent, with an L2 evict-last cache policy (keeps the
// adj lines preferentially resident for intra-run duplicate hits).
__device__ __forceinline__ float ldg_evict_last(const float* p, unsigned long long pol) {
    float v;
    asm volatile("ld.global.nc.L2::cache_hint.f32 %0, [%1], %2;"
                 : "=f"(v) : "l"(p), "l"(pol));
    return v;
}

__global__ void __launch_bounds__(NTHREADS)
fused_loss_kernel(const float* __restrict__ adj,
                  const int*   __restrict__ edge_index,   // [2, E]
                  const int*   __restrict__ neg_edges,    // [E, 2]
                  const float* __restrict__ codebook,
                  float*       __restrict__ out)
{
    const int tid = threadIdx.x;
    const int bid = blockIdx.x;
    const int e0  = bid * EPB + EPT * tid;   // this thread: edges e0..e0+7

    unsigned long long pol;
    asm volatile("createpolicy.fractional.L2::evict_last.b64 %0, 1.0;" : "=l"(pol));

    // ---- Phase 1: coalesced vector index loads, then 16 gathers back-to-back ----
    const int4 sA = __ldg((const int4*)&edge_index[e0]);
    const int4 sB = __ldg((const int4*)&edge_index[e0 + 4]);
    const int4 dA = __ldg((const int4*)&edge_index[NE + e0]);
    const int4 dB = __ldg((const int4*)&edge_index[NE + e0 + 4]);
    const int4 n0 = __ldg((const int4*)&neg_edges[2 * e0]);       // (r,c) pairs 0,1
    const int4 n1 = __ldg((const int4*)&neg_edges[2 * e0 + 4]);   // pairs 2,3
    const int4 n2 = __ldg((const int4*)&neg_edges[2 * e0 + 8]);   // pairs 4,5
    const int4 n3 = __ldg((const int4*)&neg_edges[2 * e0 + 12]);  // pairs 6,7

    // 32-bit flat indices (N*N = 2^26). All 16 gathers issued before any use.
    const float p0 = ldg_evict_last(&adj[(sA.x << NMAT_SH) + dA.x], pol);
    const float p1 = ldg_evict_last(&adj[(sA.y << NMAT_SH) + dA.y], pol);
    const float p2 = ldg_evict_last(&adj[(sA.z << NMAT_SH) + dA.z], pol);
    const float p3 = ldg_evict_last(&adj[(sA.w << NMAT_SH) + dA.w], pol);
    const float p4 = ldg_evict_last(&adj[(sB.x << NMAT_SH) + dB.x], pol);
    const float p5 = ldg_evict_last(&adj[(sB.y << NMAT_SH) + dB.y], pol);
    const float p6 = ldg_evict_last(&adj[(sB.z << NMAT_SH) + dB.z], pol);
    const float p7 = ldg_evict_last(&adj[(sB.w << NMAT_SH) + dB.w], pol);
    const float q0 = ldg_evict_last(&adj[(n0.x << NMAT_SH) + n0.y], pol);
    const float q1 = ldg_evict_last(&adj[(n0.z << NMAT_SH) + n0.w], pol);
    const float q2 = ldg_evict_last(&adj[(n1.x << NMAT_SH) + n1.y], pol);
    const float q3 = ldg_evict_last(&adj[(n1.z << NMAT_SH) + n1.w], pol);
    const float q4 = ldg_evict_last(&adj[(n2.x << NMAT_SH) + n2.y], pol);
    const float q5 = ldg_evict_last(&adj[(n2.z << NMAT_SH) + n2.w], pol);
    const float q6 = ldg_evict_last(&adj[(n3.x << NMAT_SH) + n3.y], pol);
    const float q7 = ldg_evict_last(&adj[(n3.z << NMAT_SH) + n3.w], pol);

    // ---- Phase 2: fold 16 terms into FOUR logs (each 4-term product in [1e-32,1]) ----
    float pr0 = ((p0 + EPSV) * (p1 + EPSV)) * ((p2 + EPSV) * (p3 + EPSV));
    float pr1 = ((p4 + EPSV) * (p5 + EPSV)) * ((p6 + EPSV) * (p7 + EPSV));
    float qr0 = ((1.0f - q0 + EPSV) * (1.0f - q1 + EPSV))
              * ((1.0f - q2 + EPSV) * (1.0f - q3 + EPSV));
    float qr1 = ((1.0f - q4 + EPSV) * (1.0f - q5 + EPSV))
              * ((1.0f - q6 + EPSV) * (1.0f - q7 + EPSV));
    float acc = (__logf(pr0) + __logf(pr1)) + (__logf(qr0) + __logf(qr1));

    // ---- Phase 3: warp + block reduction ----
#pragma unroll
    for (int off = 16; off > 0; off >>= 1)
        acc += __shfl_down_sync(0xFFFFFFFFu, acc, off);

    __shared__ float s_acc[NTHREADS / 32];
    const int lane = tid & 31;
    const int wid  = tid >> 5;
    if (lane == 0) s_acc[wid] = acc;
    __syncthreads();

    if (tid == 0) {
        double dsum = 0.0;
#pragma unroll
        for (int w = 0; w < NTHREADS / 32; w++) dsum += (double)s_acc[w];

        // Exact, order-independent integer accumulation (deterministic).
        atomicAdd(&g_acc, (unsigned long long)llrint(dsum * FXSCALE));
        __threadfence();
        unsigned int ticket = atomicAdd(&g_count, 1u);

        // ---- Phase 4: last block finalizes (tiny tail) ----
        if (ticket == NBLOCKS - 1) {
            unsigned long long u = atomicAdd(&g_acc, 0ULL);   // strong read
            double total = (double)(long long)u / FXSCALE;
            double loss  = -total / (double)NE
                         + (double)codebook[0] + (double)codebook[1]
                         + (double)codebook[2] + (double)codebook[3];
            out[0] = (float)loss;
            // Reset scratch for next graph replay (stream-ordered).
            g_acc = 0ULL;
            __threadfence();
            g_count = 0;
        }
    }
}

extern "C" void kernel_launch(void* const* d_in, const int* in_sizes, int n_in,
                              void* d_out, int out_size)
{
    const float* adj        = (const float*)d_in[0];   // [N*N] fp32
    const float* codebook   = (const float*)d_in[1];   // [6] fp32
    const int*   edge_index = (const int*)d_in[2];     // [2*E] int32
    const int*   neg_edges  = (const int*)d_in[3];     // [E*2] int32
    float* out = (float*)d_out;

    fused_loss_kernel<<<NBLOCKS, NTHREADS>>>(adj, edge_index, neg_edges, codebook, out);
}